// round 3
// baseline (speedup 1.0000x reference)
#include <cuda_runtime.h>
#include <cstdint>

#define IMG_S 128
#define NPIX (IMG_S * IMG_S)
#define MAXF 4096
#define Z_NEAR 0.1f
#define Z_FAR 100.0f
#define SENTINEL 0xFFFFFFFFFFFFFFFFull

// ---- scratch (no cudaMalloc allowed) ----
__device__ unsigned long long g_zbuf[NPIX];
__device__ float4 g_colors[MAXF];
__device__ float g_gray[NPIX];

// ---------------------------------------------------------------------------
__global__ void k_init_zbuf() {
    int i = blockIdx.x * blockDim.x + threadIdx.x;
    if (i < NPIX) g_zbuf[i] = SENTINEL;
}

// ---------------------------------------------------------------------------
__device__ __forceinline__ float3 project_vert(float3 p,
                                               const float* __restrict__ R,
                                               const float* __restrict__ t,
                                               const float* __restrict__ K) {
    // v_i = sum_j vert_j * R[i][j] + t[i]   (einsum 'bnj,bij->bni' + t)
    float vx = R[0] * p.x + R[1] * p.y + R[2] * p.z + t[0];
    float vy = R[3] * p.x + R[4] * p.y + R[5] * p.z + t[1];
    float vz = R[6] * p.x + R[7] * p.y + R[8] * p.z + t[2];
    float zd = vz + 1e-9f;
    float xn = vx / zd;
    float yn = vy / zd;
    // uvw = h @ K^T, h = [xn, yn, 1]
    float u = K[0] * xn + K[1] * yn + K[2];
    float v = K[3] * xn + K[4] * yn + K[5];
    float S = (float)IMG_S;
    float uu  = 2.0f * (u - S * 0.5f) / S;
    float vfl = S - v;
    float vvn = 2.0f * (vfl - S * 0.5f) / S;
    return make_float3(uu, vvn, vz);
}

// One warp per face: setup (redundant across lanes, cheap) + bbox raster.
__global__ void k_raster(const float* __restrict__ verts,
                         const int*   __restrict__ faces,
                         const float* __restrict__ tex,   // (F,3) effective
                         const float* __restrict__ R,
                         const float* __restrict__ t,
                         const float* __restrict__ K,
                         const float* __restrict__ Ldir,
                         const float* __restrict__ idir_p,
                         const float* __restrict__ iamb_p,
                         int F) {
    int wid  = (blockIdx.x * blockDim.x + threadIdx.x) >> 5;
    int lane = threadIdx.x & 31;
    if (wid >= F) return;
    int f = wid;

    int i0 = faces[3 * f + 0];
    int i1 = faces[3 * f + 1];
    int i2 = faces[3 * f + 2];

    float3 A = make_float3(verts[3 * i0], verts[3 * i0 + 1], verts[3 * i0 + 2]);
    float3 B = make_float3(verts[3 * i1], verts[3 * i1 + 1], verts[3 * i1 + 2]);
    float3 C = make_float3(verts[3 * i2], verts[3 * i2 + 1], verts[3 * i2 + 2]);

    // ---- lighting (world space) ----
    float3 v10 = make_float3(A.x - B.x, A.y - B.y, A.z - B.z);
    float3 v12 = make_float3(C.x - B.x, C.y - B.y, C.z - B.z);
    float nx = v10.y * v12.z - v10.z * v12.y;
    float ny = v10.z * v12.x - v10.x * v12.z;
    float nz = v10.x * v12.y - v10.y * v12.x;
    float nrm = sqrtf(nx * nx + ny * ny + nz * nz);
    float inv = 1.0f / fmaxf(nrm, 1e-5f);
    nx *= inv; ny *= inv; nz *= inv;
    float cosv = fmaxf(0.0f, nx * Ldir[0] + ny * Ldir[1] + nz * Ldir[2]);
    float light = iamb_p[0] + idir_p[0] * cosv;
    if (lane == 0) {
        g_colors[f] = make_float4(tex[3 * f + 0] * light,
                                  tex[3 * f + 1] * light,
                                  tex[3 * f + 2] * light, 0.0f);
    }

    // ---- projection ----
    float3 p0 = project_vert(A, R, t, K);
    float3 p1 = project_vert(B, R, t, K);
    float3 p2 = project_vert(C, R, t, K);
    float z0 = p0.z, z1 = p1.z, z2 = p2.z;

    // ---- bbox in pixel space.  px = (2x+1-S)/S  ->  x = (px*S + S - 1)/2 ----
    float Sf = (float)IMG_S;
    float minu = fminf(fminf(p0.x, p1.x), p2.x);
    float maxu = fmaxf(fmaxf(p0.x, p1.x), p2.x);
    float minv = fminf(fminf(p0.y, p1.y), p2.y);
    float maxv = fmaxf(fmaxf(p0.y, p1.y), p2.y);
    int x0 = max(0,         (int)floorf((minu * Sf + Sf - 1.0f) * 0.5f));
    int x1 = min(IMG_S - 1, (int)ceilf ((maxu * Sf + Sf - 1.0f) * 0.5f));
    int y0 = max(0,         (int)floorf((minv * Sf + Sf - 1.0f) * 0.5f));
    int y1 = min(IMG_S - 1, (int)ceilf ((maxv * Sf + Sf - 1.0f) * 0.5f));
    if (x0 > x1 || y0 > y1) return;

    int bw = x1 - x0 + 1;
    int bh = y1 - y0 + 1;
    int total = bw * bh;

    // edge deltas (constant per face, but same algebra as reference)
    float e0x = p2.x - p1.x, e0y = p2.y - p1.y;   // edge(v1,v2)
    float e1x = p0.x - p2.x, e1y = p0.y - p2.y;   // edge(v2,v0)
    float e2x = p1.x - p0.x, e2y = p1.y - p0.y;   // edge(v0,v1)

    for (int i = lane; i < total; i += 32) {
        int x = x0 + (i % bw);
        int y = y0 + (i / bw);
        float px = (2.0f * x + 1.0f - Sf) / Sf;
        float py = (2.0f * y + 1.0f - Sf) / Sf;

        float w0 = e0x * (py - p1.y) - e0y * (px - p1.x);
        float w1 = e1x * (py - p2.y) - e1y * (px - p2.x);
        float w2 = e2x * (py - p0.y) - e2y * (px - p0.x);
        float area = w0 + w1 + w2;
        bool ok = fabsf(area) > 1e-10f;
        bool ins = ((w0 >= 0.0f && w1 >= 0.0f && w2 >= 0.0f) ||
                    (w0 <= 0.0f && w1 <= 0.0f && w2 <= 0.0f)) && ok;
        if (!ins) continue;
        float ia = 1.0f / area;
        float s = (w0 * ia) / z0 + (w1 * ia) / z1 + (w2 * ia) / z2 + 1e-12f;
        float zp = 1.0f / s;
        if (zp > Z_NEAR && zp < Z_FAR) {
            unsigned long long key =
                ((unsigned long long)__float_as_uint(zp) << 32) | (unsigned int)f;
            atomicMin(&g_zbuf[y * IMG_S + x], key);
        }
    }
}

// ---------------------------------------------------------------------------
__global__ void k_resolve(float* __restrict__ out) {
    int p = blockIdx.x * blockDim.x + threadIdx.x;
    if (p >= NPIX) return;
    unsigned long long key = g_zbuf[p];
    float r = 0.0f, g = 0.0f, b = 0.0f;
    if (key != SENTINEL) {
        int f = (int)(unsigned int)(key & 0xFFFFFFFFull);
        float4 c = g_colors[f];
        r = c.x; g = c.y; b = c.z;
    }
    out[1 + 0 * NPIX + p] = r;
    out[1 + 1 * NPIX + p] = g;
    out[1 + 2 * NPIX + p] = b;
    g_gray[p] = r + g + b;
}

// ---------------------------------------------------------------------------
__global__ void k_loss(const float* __restrict__ mimg,
                       const float* __restrict__ mask,
                       float* __restrict__ out) {
    __shared__ float sm[256];
    int tid = threadIdx.x;

    // pass 1: max of gray
    float mx = -1e30f;
    for (int p = tid; p < NPIX; p += 256) mx = fmaxf(mx, g_gray[p]);
    sm[tid] = mx;
    __syncthreads();
    for (int s = 128; s > 0; s >>= 1) {
        if (tid < s) sm[tid] = fmaxf(sm[tid], sm[tid + s]);
        __syncthreads();
    }
    float maxv = sm[0];
    __syncthreads();

    // pass 2: sums
    float s1 = 0.0f, s2 = 0.0f;
    for (int p = tid; p < NPIX; p += 256) {
        float d = g_gray[p] / maxv - mimg[p];
        s1 += d * d;
        s2 += mask[p];
    }
    sm[tid] = s1;
    __syncthreads();
    for (int s = 128; s > 0; s >>= 1) {
        if (tid < s) sm[tid] += sm[tid + s];
        __syncthreads();
    }
    float S1 = sm[0];
    __syncthreads();
    sm[tid] = s2;
    __syncthreads();
    for (int s = 128; s > 0; s >>= 1) {
        if (tid < s) sm[tid] += sm[tid + s];
        __syncthreads();
    }
    float S2 = sm[0];
    if (tid == 0) out[0] = S1 / S2;
}

// ---------------------------------------------------------------------------
extern "C" void kernel_launch(void* const* d_in, const int* in_sizes, int n_in,
                              void* d_out, int out_size) {
    const float* verts = (const float*)d_in[0];   // (1,N,3)
    const int*   faces = (const int*)  d_in[1];   // (1,F,3)
    const float* tex   = (const float*)d_in[2];   // (1,F,1,1,1,3)
    const float* R     = (const float*)d_in[3];   // (1,3,3)
    const float* t     = (const float*)d_in[4];   // (1,1,3)
    const float* K     = (const float*)d_in[5];   // (3,3)
    const float* mimg  = (const float*)d_in[6];   // (128,128)
    const float* mask  = (const float*)d_in[7];   // (128,128)
    const float* Ldir  = (const float*)d_in[8];   // (3,)
    const float* idir  = (const float*)d_in[9];   // scalar
    const float* iamb  = (const float*)d_in[10];  // scalar
    float* out = (float*)d_out;

    int F = in_sizes[1] / 3;

    k_init_zbuf<<<(NPIX + 255) / 256, 256>>>();
    int threads = 128;                         // 4 warps = 4 faces per block
    int blocks  = (F * 32 + threads - 1) / threads;
    k_raster<<<blocks, threads>>>(verts, faces, tex, R, t, K, Ldir, idir, iamb, F);
    k_resolve<<<(NPIX + 255) / 256, 256>>>(out);
    k_loss<<<1, 256>>>(mimg, mask, out);
}

// round 4
// speedup vs baseline: 1.5691x; 1.5691x over previous
#include <cuda_runtime.h>
#include <cstdint>

#define IMG_S 128
#define NPIX (IMG_S * IMG_S)
#define MAXF 4096
#define Z_NEAR 0.1f
#define Z_FAR 100.0f
#define SENTINEL 0xFFFFFFFFFFFFFFFFull

// ---- scratch (no cudaMalloc allowed) ----
__device__ unsigned long long g_zbuf[NPIX];
__device__ float4 g_colors[MAXF];
__device__ float g_gray[NPIX];
__device__ int g_maxbits;   // float max of g_gray as int bits (non-negative)

// ---------------------------------------------------------------------------
__global__ void k_init_zbuf() {
    int i = blockIdx.x * blockDim.x + threadIdx.x;
    if (i < NPIX) g_zbuf[i] = SENTINEL;
    if (i == 0) g_maxbits = 0;
}

// ---------------------------------------------------------------------------
__device__ __forceinline__ float3 project_vert(float3 p,
                                               const float* __restrict__ R,
                                               const float* __restrict__ t,
                                               const float* __restrict__ K) {
    float vx = R[0] * p.x + R[1] * p.y + R[2] * p.z + t[0];
    float vy = R[3] * p.x + R[4] * p.y + R[5] * p.z + t[1];
    float vz = R[6] * p.x + R[7] * p.y + R[8] * p.z + t[2];
    float zd = vz + 1e-9f;
    float xn = vx / zd;
    float yn = vy / zd;
    float u = K[0] * xn + K[1] * yn + K[2];
    float v = K[3] * xn + K[4] * yn + K[5];
    float S = (float)IMG_S;
    float uu  = 2.0f * (u - S * 0.5f) / S;
    float vfl = S - v;
    float vvn = 2.0f * (vfl - S * 0.5f) / S;
    return make_float3(uu, vvn, vz);
}

// One warp per face: setup (redundant across lanes, cheap) + bbox raster.
__global__ void k_raster(const float* __restrict__ verts,
                         const int*   __restrict__ faces,
                         const float* __restrict__ tex,
                         const float* __restrict__ R,
                         const float* __restrict__ t,
                         const float* __restrict__ K,
                         const float* __restrict__ Ldir,
                         const float* __restrict__ idir_p,
                         const float* __restrict__ iamb_p,
                         int F) {
    int wid  = (blockIdx.x * blockDim.x + threadIdx.x) >> 5;
    int lane = threadIdx.x & 31;
    if (wid >= F) return;
    int f = wid;

    int i0 = faces[3 * f + 0];
    int i1 = faces[3 * f + 1];
    int i2 = faces[3 * f + 2];

    float3 A = make_float3(verts[3 * i0], verts[3 * i0 + 1], verts[3 * i0 + 2]);
    float3 B = make_float3(verts[3 * i1], verts[3 * i1 + 1], verts[3 * i1 + 2]);
    float3 C = make_float3(verts[3 * i2], verts[3 * i2 + 1], verts[3 * i2 + 2]);

    // ---- lighting (world space) ----
    float3 v10 = make_float3(A.x - B.x, A.y - B.y, A.z - B.z);
    float3 v12 = make_float3(C.x - B.x, C.y - B.y, C.z - B.z);
    float nx = v10.y * v12.z - v10.z * v12.y;
    float ny = v10.z * v12.x - v10.x * v12.z;
    float nz = v10.x * v12.y - v10.y * v12.x;
    float nrm = sqrtf(nx * nx + ny * ny + nz * nz);
    float inv = 1.0f / fmaxf(nrm, 1e-5f);
    nx *= inv; ny *= inv; nz *= inv;
    float cosv = fmaxf(0.0f, nx * Ldir[0] + ny * Ldir[1] + nz * Ldir[2]);
    float light = iamb_p[0] + idir_p[0] * cosv;
    if (lane == 0) {
        g_colors[f] = make_float4(tex[3 * f + 0] * light,
                                  tex[3 * f + 1] * light,
                                  tex[3 * f + 2] * light, 0.0f);
    }

    // ---- projection ----
    float3 p0 = project_vert(A, R, t, K);
    float3 p1 = project_vert(B, R, t, K);
    float3 p2 = project_vert(C, R, t, K);
    float z0 = p0.z, z1 = p1.z, z2 = p2.z;

    // ---- bbox in pixel space ----
    float Sf = (float)IMG_S;
    float minu = fminf(fminf(p0.x, p1.x), p2.x);
    float maxu = fmaxf(fmaxf(p0.x, p1.x), p2.x);
    float minv = fminf(fminf(p0.y, p1.y), p2.y);
    float maxv = fmaxf(fmaxf(p0.y, p1.y), p2.y);
    int x0 = max(0,         (int)floorf((minu * Sf + Sf - 1.0f) * 0.5f));
    int x1 = min(IMG_S - 1, (int)ceilf ((maxu * Sf + Sf - 1.0f) * 0.5f));
    int y0 = max(0,         (int)floorf((minv * Sf + Sf - 1.0f) * 0.5f));
    int y1 = min(IMG_S - 1, (int)ceilf ((maxv * Sf + Sf - 1.0f) * 0.5f));
    if (x0 > x1 || y0 > y1) return;

    int bw = x1 - x0 + 1;
    int bh = y1 - y0 + 1;
    int total = bw * bh;

    float e0x = p2.x - p1.x, e0y = p2.y - p1.y;   // edge(v1,v2)
    float e1x = p0.x - p2.x, e1y = p0.y - p2.y;   // edge(v2,v0)
    float e2x = p1.x - p0.x, e2y = p1.y - p0.y;   // edge(v0,v1)

    for (int i = lane; i < total; i += 32) {
        int x = x0 + (i % bw);
        int y = y0 + (i / bw);
        float px = (2.0f * x + 1.0f - Sf) / Sf;
        float py = (2.0f * y + 1.0f - Sf) / Sf;

        float w0 = e0x * (py - p1.y) - e0y * (px - p1.x);
        float w1 = e1x * (py - p2.y) - e1y * (px - p2.x);
        float w2 = e2x * (py - p0.y) - e2y * (px - p0.x);
        float area = w0 + w1 + w2;
        bool ok = fabsf(area) > 1e-10f;
        bool ins = ((w0 >= 0.0f && w1 >= 0.0f && w2 >= 0.0f) ||
                    (w0 <= 0.0f && w1 <= 0.0f && w2 <= 0.0f)) && ok;
        if (!ins) continue;
        float ia = 1.0f / area;
        float s = (w0 * ia) / z0 + (w1 * ia) / z1 + (w2 * ia) / z2 + 1e-12f;
        float zp = 1.0f / s;
        if (zp > Z_NEAR && zp < Z_FAR) {
            unsigned long long key =
                ((unsigned long long)__float_as_uint(zp) << 32) | (unsigned int)f;
            atomicMin(&g_zbuf[y * IMG_S + x], key);
        }
    }
}

// ---------------------------------------------------------------------------
// Resolve z-buffer -> RGB + gray, and fold in the global gray-max via
// bitwise atomicMax (exact + order-independent for non-negative floats).
__global__ void k_resolve(float* __restrict__ out) {
    int p = blockIdx.x * blockDim.x + threadIdx.x;
    unsigned long long key = g_zbuf[p];
    float r = 0.0f, g = 0.0f, b = 0.0f;
    if (key != SENTINEL) {
        int f = (int)(unsigned int)(key & 0xFFFFFFFFull);
        float4 c = g_colors[f];
        r = c.x; g = c.y; b = c.z;
    }
    out[1 + 0 * NPIX + p] = r;
    out[1 + 1 * NPIX + p] = g;
    out[1 + 2 * NPIX + p] = b;
    float gray = r + g + b;
    g_gray[p] = gray;

    // block-wide max -> one atomicMax per block
    int lane = threadIdx.x & 31;
    int wrp  = threadIdx.x >> 5;
    float mx = gray;
    #pragma unroll
    for (int o = 16; o > 0; o >>= 1)
        mx = fmaxf(mx, __shfl_down_sync(0xFFFFFFFFu, mx, o));
    __shared__ float sm[8];
    if (lane == 0) sm[wrp] = mx;
    __syncthreads();
    if (threadIdx.x == 0) {
        float m = sm[0];
        #pragma unroll
        for (int w = 1; w < 8; w++) m = fmaxf(m, sm[w]);
        atomicMax(&g_maxbits, __float_as_int(m));
    }
}

// ---------------------------------------------------------------------------
// Wide loss kernel: 1024 threads, float4 loads, shuffle+smem reduction.
__global__ void k_loss(const float* __restrict__ mimg,
                       const float* __restrict__ mask,
                       float* __restrict__ out) {
    const int tid  = threadIdx.x;
    const int lane = tid & 31;
    const int wrp  = tid >> 5;
    float maxv = __int_as_float(g_maxbits);

    const float4* g4 = (const float4*)g_gray;
    const float4* m4 = (const float4*)mimg;
    const float4* k4 = (const float4*)mask;

    float s1 = 0.0f, s2 = 0.0f;
    #pragma unroll
    for (int i = tid; i < NPIX / 4; i += 1024) {
        float4 g  = g4[i];
        float4 m  = m4[i];
        float4 km = k4[i];
        float d0 = g.x / maxv - m.x;
        float d1 = g.y / maxv - m.y;
        float d2 = g.z / maxv - m.z;
        float d3 = g.w / maxv - m.w;
        s1 += d0 * d0 + d1 * d1 + d2 * d2 + d3 * d3;
        s2 += km.x + km.y + km.z + km.w;
    }

    #pragma unroll
    for (int o = 16; o > 0; o >>= 1) {
        s1 += __shfl_down_sync(0xFFFFFFFFu, s1, o);
        s2 += __shfl_down_sync(0xFFFFFFFFu, s2, o);
    }
    __shared__ float sa[32], sb[32];
    if (lane == 0) { sa[wrp] = s1; sb[wrp] = s2; }
    __syncthreads();
    if (wrp == 0) {
        s1 = sa[lane];
        s2 = sb[lane];
        #pragma unroll
        for (int o = 16; o > 0; o >>= 1) {
            s1 += __shfl_down_sync(0xFFFFFFFFu, s1, o);
            s2 += __shfl_down_sync(0xFFFFFFFFu, s2, o);
        }
        if (lane == 0) out[0] = s1 / s2;
    }
}

// ---------------------------------------------------------------------------
extern "C" void kernel_launch(void* const* d_in, const int* in_sizes, int n_in,
                              void* d_out, int out_size) {
    const float* verts = (const float*)d_in[0];
    const int*   faces = (const int*)  d_in[1];
    const float* tex   = (const float*)d_in[2];
    const float* R     = (const float*)d_in[3];
    const float* t     = (const float*)d_in[4];
    const float* K     = (const float*)d_in[5];
    const float* mimg  = (const float*)d_in[6];
    const float* mask  = (const float*)d_in[7];
    const float* Ldir  = (const float*)d_in[8];
    const float* idir  = (const float*)d_in[9];
    const float* iamb  = (const float*)d_in[10];
    float* out = (float*)d_out;

    int F = in_sizes[1] / 3;

    k_init_zbuf<<<(NPIX + 255) / 256, 256>>>();
    int threads = 128;
    int blocks  = (F * 32 + threads - 1) / threads;
    k_raster<<<blocks, threads>>>(verts, faces, tex, R, t, K, Ldir, idir, iamb, F);
    k_resolve<<<NPIX / 256, 256>>>(out);
    k_loss<<<1, 1024>>>(mimg, mask, out);
}